// round 7
// baseline (speedup 1.0000x reference)
#include <cuda_runtime.h>
#include <cuda_fp16.h>
#include <cstdint>

// AxialAttention: 512 independent attention problems of [S=512, c=64].
// B' = outer*8 + W; q/k/v/out element (B', s, c) at outer*262144 + s*512 + W*64 + c.
// attn output [B',512,512] contiguous, placed after `out` in d_out.
// R7: persistent K/V — full 512-row K and V staged once as fp16 in smem per CTA,
// CTA loops over 8 query tiles (32 rows). Register-resident scores (R4 layout,
// no spill at 1 CTA/SM), ldmatrix fragment loads, cross-warp O reduction.

#define BSTRH 72           // K/V smem row stride (halves)
#define QSTRH 72           // Q smem row stride (halves)
#define OPSTR 68           // O partial row stride (floats)
#define QROWS 32
#define NTILES 8
// float offsets
#define KS_F 0
#define VS_F 18432         // 512*72/2
#define QS_F 36864
#define OP_F 37440         // + 32*72/2
#define RED_F 46144        // + 8*16*68
#define SMEM_FLOATS 46400
#define NEG_INF __int_as_float(0xff800000)

__device__ __forceinline__ uint32_t packh2(float a, float b) {
    __half2 h = __floats2half2_rn(a, b);
    return *reinterpret_cast<uint32_t*>(&h);
}

__device__ __forceinline__ void mma16(float* c,
        uint32_t a0, uint32_t a1, uint32_t a2, uint32_t a3,
        uint32_t b0, uint32_t b1) {
    asm volatile(
        "mma.sync.aligned.m16n8k16.row.col.f32.f16.f16.f32 "
        "{%0,%1,%2,%3},{%4,%5,%6,%7},{%8,%9},{%0,%1,%2,%3};\n"
        : "+f"(c[0]), "+f"(c[1]), "+f"(c[2]), "+f"(c[3])
        : "r"(a0), "r"(a1), "r"(a2), "r"(a3), "r"(b0), "r"(b1));
}

__device__ __forceinline__ void ldsm4(uint32_t& r0, uint32_t& r1,
                                      uint32_t& r2, uint32_t& r3, uint32_t a) {
    asm volatile("ldmatrix.sync.aligned.m8n8.x4.shared.b16 {%0,%1,%2,%3}, [%4];\n"
        : "=r"(r0), "=r"(r1), "=r"(r2), "=r"(r3) : "r"(a));
}

__device__ __forceinline__ void ldsm4t(uint32_t& r0, uint32_t& r1,
                                       uint32_t& r2, uint32_t& r3, uint32_t a) {
    asm volatile("ldmatrix.sync.aligned.m8n8.x4.trans.shared.b16 {%0,%1,%2,%3}, [%4];\n"
        : "=r"(r0), "=r"(r1), "=r"(r2), "=r"(r3) : "r"(a));
}

__global__ __launch_bounds__(256, 1)
void axial_attn_kernel(const float* __restrict__ q,
                       const float* __restrict__ k,
                       const float* __restrict__ v,
                       const int*   __restrict__ amask,
                       const float* __restrict__ hmask,
                       float* __restrict__ outp,
                       float* __restrict__ attnp)
{
    extern __shared__ float sm[];
    __half* Ks  = (__half*)(sm + KS_F);    // 512 x 72 halves
    __half* Vs  = (__half*)(sm + VS_F);    // 512 x 72 halves
    __half* Qs  = (__half*)(sm + QS_F);    // 32 x 72 halves
    float*  Op  = sm + OP_F;               // 8 warps x 16 x OPSTR
    float*  red = sm + RED_F;              // [2][4cg][32rows]

    const int tid  = threadIdx.x;
    const int w    = tid >> 5;
    const int lane = tid & 31;
    const int gid  = lane >> 2;
    const int tig  = lane & 3;
    const int rg   = w >> 2;       // row group (0/1) -> 16 rows
    const int cg   = w & 3;        // col group (0..3) -> 16 cols within 64-chunk
    const int m0   = rg * 16;
    const int cb   = cg * 16 + 2 * tig;

    const int Bp = blockIdx.y;
    const int hx = blockIdx.x;     // tile half (0/1)
    const int outer = Bp >> 3;
    const int Wd    = Bp & 7;
    const long base = (long)outer * 262144 + (long)Wd * 64;

    const float* qb = q + base;
    const float* kb = k + base;
    const float* vb = v + base;
    float* ob = outp + base;
    float* ab = attnp + (long)Bp * 262144;

    // ---- stage full K and V as fp16 (once per CTA) ----
    #pragma unroll 4
    for (int i = 0; i < 32; i++) {
        int e  = tid + 256 * i;
        int r  = e >> 4;
        int c4 = (e & 15) << 2;
        float4 tk = *(const float4*)(kb + (long)r * 512 + c4);
        float4 tv = *(const float4*)(vb + (long)r * 512 + c4);
        *(uint2*)(Ks + r * BSTRH + c4) = make_uint2(packh2(tk.x, tk.y), packh2(tk.z, tk.w));
        *(uint2*)(Vs + r * BSTRH + c4) = make_uint2(packh2(tv.x, tv.y), packh2(tv.z, tv.w));
    }

    // ldmatrix lane addressing
    const uint32_t ksA = (uint32_t)__cvta_generic_to_shared(Ks);
    const uint32_t vsA = (uint32_t)__cvta_generic_to_shared(Vs);
    const int krow_l  = cg * 16 + ((lane >> 3) & 1) * 8 + (lane & 7);
    const int choff_l = ((lane >> 4) & 1) * 8;
    const uint32_t kaddr0 = ksA + (uint32_t)(krow_l * BSTRH + choff_l) * 2;
    const int vrow_l = ((lane >> 3) & 1) * 8 + (lane & 7);
    const uint32_t vaddr0 = vsA + (uint32_t)((cg * 16 + vrow_l) * BSTRH + choff_l) * 2;

    // ---- loop over 8 query tiles of 32 rows ----
    for (int t = 0; t < NTILES; t++) {
        const int q0  = (hx * NTILES + t) * QROWS;
        const int qlo = q0 + m0 + gid;
        const int qhi = qlo + 8;

        __syncthreads();   // Qs/Op free (prev tile consumers done); covers staging on t=0

        // -- stage Q tile (scale 0.125, fp16) --
        #pragma unroll
        for (int i = 0; i < 2; i++) {
            int e  = tid + 256 * i;
            int r  = e >> 4;
            int c4 = (e & 15) << 2;
            float4 tq = *(const float4*)(qb + (long)(q0 + r) * 512 + c4);
            *(uint2*)(Qs + r * QSTRH + c4) =
                make_uint2(packh2(tq.x * 0.125f, tq.y * 0.125f),
                           packh2(tq.z * 0.125f, tq.w * 0.125f));
        }
        __syncthreads();

        // -- A fragments --
        uint32_t A[4][4];
        #pragma unroll
        for (int ks = 0; ks < 4; ks++) {
            const __half* qr = Qs + (m0 + gid) * QSTRH + ks * 16 + 2 * tig;
            A[ks][0] = *(const uint32_t*)(qr);
            A[ks][1] = *(const uint32_t*)(qr + 8 * QSTRH);
            A[ks][2] = *(const uint32_t*)(qr + 8);
            A[ks][3] = *(const uint32_t*)(qr + 8 * QSTRH + 8);
        }

        // -- QK^T: scores in registers --
        float C[8][2][4];
        #pragma unroll
        for (int kc = 0; kc < 8; kc++) {
            #pragma unroll
            for (int nt = 0; nt < 2; nt++)
                #pragma unroll
                for (int i = 0; i < 4; i++) C[kc][nt][i] = 0.f;
            uint32_t ka = kaddr0 + (uint32_t)kc * (64 * BSTRH * 2);
            #pragma unroll
            for (int ks = 0; ks < 4; ks++) {
                uint32_t b0, b1, b2, b3;
                ldsm4(b0, b1, b2, b3, ka + ks * 32);
                mma16(C[kc][0], A[ks][0], A[ks][1], A[ks][2], A[ks][3], b0, b2);
                mma16(C[kc][1], A[ks][0], A[ks][1], A[ks][2], A[ks][3], b1, b3);
            }
        }

        // -- mask + row max --
        const int* mloB = amask + (long)qlo * 512;
        const int* mhiB = amask + (long)qhi * 512;
        float mxl = NEG_INF, mxh = NEG_INF;
        #pragma unroll
        for (int kc = 0; kc < 8; kc++)
            #pragma unroll
            for (int nt = 0; nt < 2; nt++) {
                int col = kc * 64 + cb + nt * 8;
                int2 ml = *(const int2*)(mloB + col);
                int2 mh = *(const int2*)(mhiB + col);
                if (ml.x == 0) C[kc][nt][0] = NEG_INF;
                if (ml.y == 0) C[kc][nt][1] = NEG_INF;
                if (mh.x == 0) C[kc][nt][2] = NEG_INF;
                if (mh.y == 0) C[kc][nt][3] = NEG_INF;
                mxl = fmaxf(mxl, fmaxf(C[kc][nt][0], C[kc][nt][1]));
                mxh = fmaxf(mxh, fmaxf(C[kc][nt][2], C[kc][nt][3]));
            }
        mxl = fmaxf(mxl, __shfl_xor_sync(0xFFFFFFFFu, mxl, 1));
        mxl = fmaxf(mxl, __shfl_xor_sync(0xFFFFFFFFu, mxl, 2));
        mxh = fmaxf(mxh, __shfl_xor_sync(0xFFFFFFFFu, mxh, 1));
        mxh = fmaxf(mxh, __shfl_xor_sync(0xFFFFFFFFu, mxh, 2));
        if (tig == 0) {
            red[cg * 32 + m0 + gid]     = mxl;
            red[cg * 32 + m0 + gid + 8] = mxh;
        }
        __syncthreads();
        float gml = fmaxf(fmaxf(red[0 * 32 + m0 + gid], red[1 * 32 + m0 + gid]),
                          fmaxf(red[2 * 32 + m0 + gid], red[3 * 32 + m0 + gid]));
        float gmh = fmaxf(fmaxf(red[0 * 32 + m0 + gid + 8], red[1 * 32 + m0 + gid + 8]),
                          fmaxf(red[2 * 32 + m0 + gid + 8], red[3 * 32 + m0 + gid + 8]));

        // -- exp + row sum --
        float sl = 0.f, sh = 0.f;
        #pragma unroll
        for (int kc = 0; kc < 8; kc++)
            #pragma unroll
            for (int nt = 0; nt < 2; nt++) {
                float e0 = __expf(C[kc][nt][0] - gml);
                float e1 = __expf(C[kc][nt][1] - gml);
                float e2 = __expf(C[kc][nt][2] - gmh);
                float e3 = __expf(C[kc][nt][3] - gmh);
                C[kc][nt][0] = e0; C[kc][nt][1] = e1;
                C[kc][nt][2] = e2; C[kc][nt][3] = e3;
                sl += e0 + e1;
                sh += e2 + e3;
            }
        sl += __shfl_xor_sync(0xFFFFFFFFu, sl, 1);
        sl += __shfl_xor_sync(0xFFFFFFFFu, sl, 2);
        sh += __shfl_xor_sync(0xFFFFFFFFu, sh, 1);
        sh += __shfl_xor_sync(0xFFFFFFFFu, sh, 2);
        if (tig == 0) {
            red[128 + cg * 32 + m0 + gid]     = sl;
            red[128 + cg * 32 + m0 + gid + 8] = sh;
        }
        __syncthreads();
        float invl = 1.0f / (red[128 + 0 * 32 + m0 + gid] + red[128 + 1 * 32 + m0 + gid] +
                             red[128 + 2 * 32 + m0 + gid] + red[128 + 3 * 32 + m0 + gid]);
        float invh = 1.0f / (red[128 + 0 * 32 + m0 + gid + 8] + red[128 + 1 * 32 + m0 + gid + 8] +
                             red[128 + 2 * 32 + m0 + gid + 8] + red[128 + 3 * 32 + m0 + gid + 8]);

        // -- head_mask, write attn from fragments, pack P in regs --
        const float* hloB = hmask + (long)qlo * 512;
        const float* hhiB = hmask + (long)qhi * 512;
        float* aloB = ab + (long)qlo * 512;
        float* ahiB = ab + (long)qhi * 512;
        uint32_t P[8][2][2];
        #pragma unroll
        for (int kc = 0; kc < 8; kc++)
            #pragma unroll
            for (int nt = 0; nt < 2; nt++) {
                int col = kc * 64 + cb + nt * 8;
                float2 hl = *(const float2*)(hloB + col);
                float2 hh = *(const float2*)(hhiB + col);
                float a0 = C[kc][nt][0] * invl * hl.x;
                float a1 = C[kc][nt][1] * invl * hl.y;
                float a2 = C[kc][nt][2] * invh * hh.x;
                float a3 = C[kc][nt][3] * invh * hh.y;
                *(float2*)(aloB + col) = make_float2(a0, a1);
                *(float2*)(ahiB + col) = make_float2(a2, a3);
                P[kc][nt][0] = packh2(a0, a1);
                P[kc][nt][1] = packh2(a2, a3);
            }

        // -- PV: per-warp partial O (16 rows x 64 ch over this warp's 128 k) --
        float O[8][4];
        #pragma unroll
        for (int nt = 0; nt < 8; nt++)
            #pragma unroll
            for (int i = 0; i < 4; i++) O[nt][i] = 0.f;

        #pragma unroll
        for (int kc = 0; kc < 8; kc++) {
            uint32_t a0 = P[kc][0][0], a1 = P[kc][0][1];
            uint32_t a2 = P[kc][1][0], a3 = P[kc][1][1];
            uint32_t va = vaddr0 + (uint32_t)kc * (64 * BSTRH * 2);
            #pragma unroll
            for (int cq = 0; cq < 4; cq++) {
                uint32_t b0, b1, b2, b3;
                ldsm4t(b0, b1, b2, b3, va + cq * 32);
                mma16(O[2 * cq],     a0, a1, a2, a3, b0, b1);
                mma16(O[2 * cq + 1], a0, a1, a2, a3, b2, b3);
            }
        }

        // -- cross-warp O reduction --
        #pragma unroll
        for (int nt = 0; nt < 8; nt++) {
            float* p0 = Op + w * (16 * OPSTR) + gid * OPSTR + nt * 8 + 2 * tig;
            *(float2*)(p0)             = make_float2(O[nt][0], O[nt][1]);
            *(float2*)(p0 + 8 * OPSTR) = make_float2(O[nt][2], O[nt][3]);
        }
        __syncthreads();
        #pragma unroll
        for (int i = 0; i < 2; i++) {
            int e   = tid + 256 * i;      // 512 float4 = 32 rows x 64 ch
            int R   = e >> 4;
            int c4  = (e & 15) << 2;
            int wb  = (R >> 4) * 4;       // row group base warp
            int rl  = R & 15;
            float4 s = *(const float4*)(Op + (wb + 0) * (16 * OPSTR) + rl * OPSTR + c4);
            #pragma unroll
            for (int j = 1; j < 4; j++) {
                float4 u = *(const float4*)(Op + (wb + j) * (16 * OPSTR) + rl * OPSTR + c4);
                s.x += u.x; s.y += u.y; s.z += u.z; s.w += u.w;
            }
            *(float4*)(ob + (long)(q0 + R) * 512 + c4) = s;
        }
    }
}

extern "C" void kernel_launch(void* const* d_in, const int* in_sizes, int n_in,
                              void* d_out, int out_size) {
    const float* q  = (const float*)d_in[0];
    const float* k  = (const float*)d_in[1];
    const float* v  = (const float*)d_in[2];
    const int*   am = (const int*)d_in[3];
    const float* hm = (const float*)d_in[4];

    float* out  = (float*)d_out;
    float* attn = out + (long)in_sizes[0];

    size_t smem = (size_t)SMEM_FLOATS * sizeof(float);
    cudaFuncSetAttribute(axial_attn_kernel,
                         cudaFuncAttributeMaxDynamicSharedMemorySize, (int)smem);

    dim3 grid(2, 512);   // x: tile half (8 q-tiles each), y: flattened batch B'
    axial_attn_kernel<<<grid, 256, smem>>>(q, k, v, am, hm, out, attn);
}